// round 14
// baseline (speedup 1.0000x reference)
#include <cuda_runtime.h>
#include <cstdint>

constexpr int B_ = 8;     // batch
constexpr int Q_ = 128;   // queries
constexpr int K_ = 1024;  // keys
constexpr int D_ = 512;   // qk feature dim
constexpr int H_ = 256;   // hidden
constexpr int V_ = 512;   // value dim
constexpr int MK = B_ * K_;   // 8192 rows of kproj
constexpr int SPLITS = 4;     // av split-K factor (256 k per split)

// Scratch (no cudaMalloc allowed)
__device__ float g_qproj [B_ * Q_ * H_];          // [B*Q][H]   1 MB
__device__ float g_kprojT[H_ * B_ * K_];          // [H][B*K]   8 MB
__device__ float g_scores[B_ * Q_ * K_];          // [B*Q][K]   4 MB (scores -> attn)
__device__ float g_avpart[SPLITS][B_ * Q_ * V_];  // 4 x 2 MB split-K partials

__device__ __forceinline__ float tanh_fast(float x) {
    float y;
    asm("tanh.approx.f32 %0, %1;" : "=f"(y) : "f"(x));
    return y;
}
__device__ __forceinline__ unsigned long long pack2(float lo, float hi) {
    unsigned long long r;
    asm("mov.b64 %0, {%1, %2};" : "=l"(r) : "f"(lo), "f"(hi));
    return r;
}
__device__ __forceinline__ float2 unpack2(unsigned long long v) {
    float2 r;
    asm("mov.b64 {%0, %1}, %2;" : "=f"(r.x), "=f"(r.y) : "l"(v));
    return r;
}
__device__ __forceinline__ unsigned long long fma2(unsigned long long a,
                                                   unsigned long long b,
                                                   unsigned long long c) {
    unsigned long long d;
    asm("fma.rn.f32x2 %0, %1, %2, %3;" : "=l"(d) : "l"(a), "l"(b), "l"(c));
    return d;
}
__device__ __forceinline__ unsigned long long add2(unsigned long long a,
                                                   unsigned long long b) {
    unsigned long long d;
    asm("add.rn.f32x2 %0, %1, %2;" : "=l"(d) : "l"(a), "l"(b));
    return d;
}
__device__ __forceinline__ uint32_t f2tf32(float x) {
    uint32_t r;
    asm("cvt.rna.tf32.f32 %0, %1;" : "=r"(r) : "f"(x));
    return r;
}
__device__ __forceinline__ void mma_tf32(float* c, const uint32_t* a, const uint32_t* b) {
    asm volatile(
        "mma.sync.aligned.m16n8k8.row.col.f32.tf32.tf32.f32 "
        "{%0,%1,%2,%3}, {%4,%5,%6,%7}, {%8,%9}, {%0,%1,%2,%3};"
        : "+f"(c[0]), "+f"(c[1]), "+f"(c[2]), "+f"(c[3])
        : "r"(a[0]), "r"(a[1]), "r"(a[2]), "r"(a[3]), "r"(b[0]), "r"(b[1]));
}

// ----------------------------------------------------------------------------
// K1: tensor-core projection GEMM — single-pass tf32 (round-12, measured 31us).
// ----------------------------------------------------------------------------
__global__ __launch_bounds__(128)
void proj_gemm(const float* __restrict__ queries, const float* __restrict__ keys,
               const float* __restrict__ Wq, const float* __restrict__ Wk,
               const int* __restrict__ vlens)
{
    constexpr int BK = 16, PAD = 72;
    __shared__ uint32_t AsHi[2][BK][PAD];
    __shared__ uint32_t Bsm [2][BK][PAD];

    const int tid = threadIdx.x;
    const bool isQ = (blockIdx.y < 16);
    const float* A;
    const float* W;
    long long row0;
    if (isQ) {
        A = queries; W = Wq; row0 = (long long)blockIdx.y * 64;
    } else {
        int r  = (int)(blockIdx.y - 16) * 64;
        int b  = r >> 10;
        int k0 = r & 1023;
        if (k0 >= vlens[b]) return;     // masked kproj tile
        A = keys; W = Wk; row0 = r;
    }
    const int col0 = blockIdx.x * 64;

    const int warp = tid >> 5, lane = tid & 31;
    const int wm = warp >> 1, wn = warp & 1;
    const int gid = lane >> 2, titg = lane & 3;
    const int m_base = wm * 32;
    const int n_base = wn * 32;

    int arow[2], ac4[2], brow[2], bc4[2];
    #pragma unroll
    for (int u = 0; u < 2; u++) {
        int l = tid * 2 + u;
        arow[u] = l >> 2;  ac4[u] = (l & 3) << 2;
        brow[u] = l >> 4;  bc4[u] = (l & 15) << 2;
    }

    float acc[2][4][4];
    #pragma unroll
    for (int mt = 0; mt < 2; mt++)
        #pragma unroll
        for (int nt = 0; nt < 4; nt++)
            #pragma unroll
            for (int i = 0; i < 4; i++) acc[mt][nt][i] = 0.0f;

    float4 avr[2], bvr[2];
    #pragma unroll
    for (int u = 0; u < 2; u++) {
        avr[u] = *(const float4*)(A + (row0 + arow[u]) * D_ + ac4[u]);
        bvr[u] = *(const float4*)(W + (long long)brow[u] * H_ + col0 + bc4[u]);
    }
    #pragma unroll
    for (int u = 0; u < 2; u++) {
        float av[4] = {avr[u].x, avr[u].y, avr[u].z, avr[u].w};
        #pragma unroll
        for (int i = 0; i < 4; i++)
            AsHi[0][ac4[u] + i][arow[u]] = f2tf32(av[i]);
        float bv[4] = {bvr[u].x, bvr[u].y, bvr[u].z, bvr[u].w};
        #pragma unroll
        for (int i = 0; i < 4; i++)
            Bsm[0][brow[u]][bc4[u] + i] = f2tf32(bv[i]);
    }
    __syncthreads();

    constexpr int NKB = D_ / BK;   // 32
    for (int it = 0; it < NKB; it++) {
        const int cur = it & 1;
        if (it + 1 < NKB) {
            const int kb = (it + 1) * BK;
            #pragma unroll
            for (int u = 0; u < 2; u++) {
                avr[u] = *(const float4*)(A + (row0 + arow[u]) * D_ + kb + ac4[u]);
                bvr[u] = *(const float4*)(W + (long long)(kb + brow[u]) * H_ + col0 + bc4[u]);
            }
        }
        #pragma unroll
        for (int ks = 0; ks < 2; ks++) {
            const int k0 = ks * 8 + titg;
            uint32_t ahi[2][4], bf[4][2];
            #pragma unroll
            for (int mt = 0; mt < 2; mt++) {
                const int m = m_base + mt * 16 + gid;
                ahi[mt][0] = AsHi[cur][k0][m];
                ahi[mt][1] = AsHi[cur][k0][m + 8];
                ahi[mt][2] = AsHi[cur][k0 + 4][m];
                ahi[mt][3] = AsHi[cur][k0 + 4][m + 8];
            }
            #pragma unroll
            for (int nt = 0; nt < 4; nt++) {
                const int n = n_base + nt * 8 + gid;
                bf[nt][0] = Bsm[cur][k0][n];
                bf[nt][1] = Bsm[cur][k0 + 4][n];
            }
            #pragma unroll
            for (int mt = 0; mt < 2; mt++)
                #pragma unroll
                for (int nt = 0; nt < 4; nt++)
                    mma_tf32(acc[mt][nt], ahi[mt], bf[nt]);
        }
        if (it + 1 < NKB) {
            const int nxt = 1 - cur;
            #pragma unroll
            for (int u = 0; u < 2; u++) {
                float av[4] = {avr[u].x, avr[u].y, avr[u].z, avr[u].w};
                #pragma unroll
                for (int i = 0; i < 4; i++)
                    AsHi[nxt][ac4[u] + i][arow[u]] = f2tf32(av[i]);
                float bv[4] = {bvr[u].x, bvr[u].y, bvr[u].z, bvr[u].w};
                #pragma unroll
                for (int i = 0; i < 4; i++)
                    Bsm[nxt][brow[u]][bc4[u] + i] = f2tf32(bv[i]);
            }
            __syncthreads();
        }
    }

    if (isQ) {
        #pragma unroll
        for (int mt = 0; mt < 2; mt++) {
            const long long r_lo = row0 + m_base + mt * 16 + gid;
            #pragma unroll
            for (int nt = 0; nt < 4; nt++) {
                const int n = col0 + n_base + nt * 8 + 2 * titg;
                *(float2*)(g_qproj + r_lo * H_ + n) =
                    make_float2(acc[mt][nt][0], acc[mt][nt][1]);
                *(float2*)(g_qproj + (r_lo + 8) * H_ + n) =
                    make_float2(acc[mt][nt][2], acc[mt][nt][3]);
            }
        }
    } else {
        #pragma unroll
        for (int mt = 0; mt < 2; mt++) {
            const long long m = row0 + m_base + mt * 16 + gid;
            #pragma unroll
            for (int nt = 0; nt < 4; nt++) {
                const long long n = col0 + n_base + nt * 8 + 2 * titg;
                g_kprojT[n * MK + m]           = acc[mt][nt][0];
                g_kprojT[(n + 1) * MK + m]     = acc[mt][nt][1];
                g_kprojT[n * MK + m + 8]       = acc[mt][nt][2];
                g_kprojT[(n + 1) * MK + m + 8] = acc[mt][nt][3];
            }
        }
    }
}

// ----------------------------------------------------------------------------
// K2: masked tanh-scores, QT=4 + warp-level mask skip (round-13 version).
// grid = (32, 4, 8), 256 threads.
// ----------------------------------------------------------------------------
__global__ __launch_bounds__(256)
void scores_kernel(const float* __restrict__ wv, const int* __restrict__ vlens)
{
    constexpr int QT = 4;
    constexpr int HC = 16;
    constexpr int NCH = H_ / HC;
    __shared__ float s_tile[2][HC][256];
    __shared__ float s_q[QT][H_];
    __shared__ float s_wv[H_];

    const int b   = blockIdx.z;
    const int kp  = blockIdx.y;
    const int q0  = blockIdx.x * QT;
    const int tid = threadIdx.x;
    const int vlen = vlens[b];
    if (kp * 256 >= vlen) return;
    const bool wactive = (kp * 256 + (tid & ~31)) < vlen;   // warp-uniform

    for (int i = tid; i < QT * H_; i += 256)
        s_q[i >> 8][i & 255] = g_qproj[(long long)(b * Q_ + q0 + (i >> 8)) * H_ + (i & 255)];
    for (int i = tid; i < H_; i += 256) s_wv[i] = wv[i];

    const float* kbase = g_kprojT + (long long)b * K_ + kp * 256;

    float4 rn[4];
    #pragma unroll
    for (int i = 0; i < 4; i++) {
        int idx = i * 256 + tid;
        int h = idx >> 6, c4 = (idx & 63) << 2;
        rn[i] = *(const float4*)(kbase + (long long)h * MK + c4);
    }
    #pragma unroll
    for (int i = 0; i < 4; i++) {
        int idx = i * 256 + tid;
        int h = idx >> 6, c4 = (idx & 63) << 2;
        *(float4*)&s_tile[0][h][c4] = rn[i];
    }
    __syncthreads();

    unsigned long long acc[QT] = {0ull, 0ull, 0ull, 0ull};

    for (int hc = 0; hc < NCH; hc++) {
        const int cur = hc & 1;
        if (hc + 1 < NCH) {
            #pragma unroll
            for (int i = 0; i < 4; i++) {
                int idx = i * 256 + tid;
                int h = idx >> 6, c4 = (idx & 63) << 2;
                rn[i] = *(const float4*)(kbase + (long long)((hc + 1) * HC + h) * MK + c4);
            }
        }
        if (wactive) {
            const int hbase = hc * HC;
            #pragma unroll
            for (int hh = 0; hh < HC; hh += 2) {
                float kv0 = s_tile[cur][hh][tid];
                float kv1 = s_tile[cur][hh + 1][tid];
                unsigned long long kvp = pack2(kv0, kv1);
                unsigned long long wvp = *(const unsigned long long*)&s_wv[hbase + hh];
                #pragma unroll
                for (int j = 0; j < QT; j++) {
                    unsigned long long qp = *(const unsigned long long*)&s_q[j][hbase + hh];
                    float2 sf = unpack2(add2(qp, kvp));
                    unsigned long long t = pack2(tanh_fast(sf.x), tanh_fast(sf.y));
                    acc[j] = fma2(t, wvp, acc[j]);
                }
            }
        }
        if (hc + 1 < NCH) {
            #pragma unroll
            for (int i = 0; i < 4; i++) {
                int idx = i * 256 + tid;
                int h = idx >> 6, c4 = (idx & 63) << 2;
                *(float4*)&s_tile[1 - cur][h][c4] = rn[i];
            }
            __syncthreads();
        }
    }

    const int k = kp * 256 + tid;
    if (k < vlen) {
        #pragma unroll
        for (int j = 0; j < QT; j++) {
            float2 r = unpack2(acc[j]);
            g_scores[(long long)(b * Q_ + q0 + j) * K_ + k] = r.x + r.y;
        }
    }
}

// ----------------------------------------------------------------------------
// K3: masked softmax — normalizes in place; zero-fills [vlen, roundup16(vlen)).
// grid = (32, 8), 256 threads.
// ----------------------------------------------------------------------------
__global__ __launch_bounds__(256)
void softmax_norm(const int* __restrict__ vlens)
{
    constexpr int QT = 4;
    __shared__ float s_sc[QT][K_];
    __shared__ float s_red[8];

    const int b   = blockIdx.y;
    const int q0  = blockIdx.x * QT;
    const int tid = threadIdx.x;
    const int lane = tid & 31;
    const int wid  = tid >> 5;
    const int vlen = vlens[b];
    const int kmax = (vlen + 15) & ~15;

    #pragma unroll
    for (int j = 0; j < QT; j++)
        for (int k = tid; k < vlen; k += 256)
            s_sc[j][k] = g_scores[(long long)(b * Q_ + q0 + j) * K_ + k];
    __syncthreads();

    #pragma unroll 1
    for (int j = 0; j < QT; j++) {
        float m = -3.4e38f;
        for (int k = tid; k < vlen; k += 256) m = fmaxf(m, s_sc[j][k]);
        #pragma unroll
        for (int off = 16; off; off >>= 1)
            m = fmaxf(m, __shfl_xor_sync(0xffffffffu, m, off));
        if (lane == 0) s_red[wid] = m;
        __syncthreads();
        float mm = s_red[0];
        #pragma unroll
        for (int w = 1; w < 8; w++) mm = fmaxf(mm, s_red[w]);
        __syncthreads();

        float s = 0.f;
        for (int k = tid; k < vlen; k += 256) {
            float e = __expf(s_sc[j][k] - mm);
            s_sc[j][k] = e;
            s += e;
        }
        #pragma unroll
        for (int off = 16; off; off >>= 1)
            s += __shfl_xor_sync(0xffffffffu, s, off);
        if (lane == 0) s_red[wid] = s;
        __syncthreads();
        float ssum = 0.f;
        #pragma unroll
        for (int w = 0; w < 8; w++) ssum += s_red[w];
        float inv = 1.0f / ssum;

        float* attn_row = g_scores + (long long)(b * Q_ + q0 + j) * K_;
        for (int k = tid; k < vlen; k += 256)
            attn_row[k] = s_sc[j][k] * inv;
        for (int k = vlen + tid; k < kmax; k += 256)
            attn_row[k] = 0.0f;
        __syncthreads();
    }
}

// ----------------------------------------------------------------------------
// K4: AV GEMM, tf32 MMA, SPLIT-K (4 x 256-k ranges) -> g_avpart[s].
// grid = (V/64=8, Q/64=2, B*SPLITS=32) = 512 blocks (~320 active).
// ----------------------------------------------------------------------------
__global__ __launch_bounds__(128)
void av_gemm(const float* __restrict__ values, const int* __restrict__ vlens)
{
    constexpr int BK = 16, PAD = 72;
    __shared__ uint32_t AsHi[2][BK][PAD];
    __shared__ uint32_t Bsm [2][BK][PAD];

    const int tid = threadIdx.x;
    const int bz = blockIdx.z;
    const int b = bz >> 2, s = bz & 3;
    const int vlen = vlens[b];
    const int kmax = (vlen + 15) & ~15;
    const int kbeg = s * 256;
    const int kend = min(kmax, kbeg + 256);
    if (kbeg >= kend) return;
    const int NKB = (kend - kbeg) / BK;   // 1..16

    const long long row0 = (long long)b * Q_ + blockIdx.y * 64;
    const int col0 = blockIdx.x * 64;
    const float* A  = g_scores + kbeg;                               // row stride K_
    const float* Bv = values + (long long)b * K_ * V_ + (long long)kbeg * V_;
    float* outp = g_avpart[s];

    const int warp = tid >> 5, lane = tid & 31;
    const int wm = warp >> 1, wn = warp & 1;
    const int gid = lane >> 2, titg = lane & 3;
    const int m_base = wm * 32;
    const int n_base = wn * 32;

    int arow[2], ac4[2], brow[2], bc4[2];
    #pragma unroll
    for (int u = 0; u < 2; u++) {
        int l = tid * 2 + u;
        arow[u] = l >> 2;  ac4[u] = (l & 3) << 2;
        brow[u] = l >> 4;  bc4[u] = (l & 15) << 2;
    }

    float acc[2][4][4];
    #pragma unroll
    for (int mt = 0; mt < 2; mt++)
        #pragma unroll
        for (int nt = 0; nt < 4; nt++)
            #pragma unroll
            for (int i = 0; i < 4; i++) acc[mt][nt][i] = 0.0f;

    float4 avr[2], bvr[2];
    #pragma unroll
    for (int u = 0; u < 2; u++) {
        avr[u] = *(const float4*)(A + (row0 + arow[u]) * K_ + ac4[u]);
        bvr[u] = *(const float4*)(Bv + (long long)brow[u] * V_ + col0 + bc4[u]);
    }
    #pragma unroll
    for (int u = 0; u < 2; u++) {
        float av[4] = {avr[u].x, avr[u].y, avr[u].z, avr[u].w};
        #pragma unroll
        for (int i = 0; i < 4; i++)
            AsHi[0][ac4[u] + i][arow[u]] = f2tf32(av[i]);
        float bv[4] = {bvr[u].x, bvr[u].y, bvr[u].z, bvr[u].w};
        #pragma unroll
        for (int i = 0; i < 4; i++)
            Bsm[0][brow[u]][bc4[u] + i] = f2tf32(bv[i]);
    }
    __syncthreads();

    for (int it = 0; it < NKB; it++) {
        const int cur = it & 1;
        if (it + 1 < NKB) {
            const int kb = (it + 1) * BK;
            #pragma unroll
            for (int u = 0; u < 2; u++) {
                avr[u] = *(const float4*)(A + (row0 + arow[u]) * K_ + kb + ac4[u]);
                bvr[u] = *(const float4*)(Bv + (long long)(kb + brow[u]) * V_ + col0 + bc4[u]);
            }
        }
        #pragma unroll
        for (int ks = 0; ks < 2; ks++) {
            const int k0 = ks * 8 + titg;
            uint32_t ahi[2][4], bf[4][2];
            #pragma unroll
            for (int mt = 0; mt < 2; mt++) {
                const int m = m_base + mt * 16 + gid;
                ahi[mt][0] = AsHi[cur][k0][m];
                ahi[mt][1] = AsHi[cur][k0][m + 8];
                ahi[mt][2] = AsHi[cur][k0 + 4][m];
                ahi[mt][3] = AsHi[cur][k0 + 4][m + 8];
            }
            #pragma unroll
            for (int nt = 0; nt < 4; nt++) {
                const int n = n_base + nt * 8 + gid;
                bf[nt][0] = Bsm[cur][k0][n];
                bf[nt][1] = Bsm[cur][k0 + 4][n];
            }
            #pragma unroll
            for (int mt = 0; mt < 2; mt++)
                #pragma unroll
                for (int nt = 0; nt < 4; nt++)
                    mma_tf32(acc[mt][nt], ahi[mt], bf[nt]);
        }
        if (it + 1 < NKB) {
            const int nxt = 1 - cur;
            #pragma unroll
            for (int u = 0; u < 2; u++) {
                float av[4] = {avr[u].x, avr[u].y, avr[u].z, avr[u].w};
                #pragma unroll
                for (int i = 0; i < 4; i++)
                    AsHi[nxt][ac4[u] + i][arow[u]] = f2tf32(av[i]);
                float bv[4] = {bvr[u].x, bvr[u].y, bvr[u].z, bvr[u].w};
                #pragma unroll
                for (int i = 0; i < 4; i++)
                    Bsm[nxt][brow[u]][bc4[u] + i] = f2tf32(bv[i]);
            }
            __syncthreads();
        }
    }

    #pragma unroll
    for (int mt = 0; mt < 2; mt++) {
        const long long r_lo = row0 + m_base + mt * 16 + gid;
        #pragma unroll
        for (int nt = 0; nt < 4; nt++) {
            const int n = col0 + n_base + nt * 8 + 2 * titg;
            *(float2*)(outp + r_lo * V_ + n) =
                make_float2(acc[mt][nt][0], acc[mt][nt][1]);
            *(float2*)(outp + (r_lo + 8) * V_ + n) =
                make_float2(acc[mt][nt][2], acc[mt][nt][3]);
        }
    }
}

// ----------------------------------------------------------------------------
// K5: split-K reduce: out = sum over active splits of g_avpart[s].
// float4-vectorized; grid = 512 x 256 covers B*Q*V/4 = 131072 float4.
// ----------------------------------------------------------------------------
__global__ __launch_bounds__(256)
void av_reduce(const int* __restrict__ vlens, float* __restrict__ out)
{
    const int idx = blockIdx.x * 256 + threadIdx.x;        // float4 index
    const int b = idx / (Q_ * V_ / 4);
    const int vlen = vlens[b];
    const int kmax = (vlen + 15) & ~15;
    const int ns = (kmax + 255) >> 8;                       // active splits, 1..4

    float4 a = *((const float4*)g_avpart[0] + idx);
    #pragma unroll 1
    for (int s = 1; s < ns; s++) {
        float4 p = *((const float4*)g_avpart[s] + idx);
        a.x += p.x; a.y += p.y; a.z += p.z; a.w += p.w;
    }
    *((float4*)out + idx) = a;
}

// ----------------------------------------------------------------------------
extern "C" void kernel_launch(void* const* d_in, const int* in_sizes, int n_in,
                              void* d_out, int out_size)
{
    const float* queries = (const float*)d_in[0];  // [B,Q,D]
    const float* keys    = (const float*)d_in[1];  // [B,K,D]
    const float* values  = (const float*)d_in[2];  // [B,K,V]
    const int*   vlens   = (const int*)  d_in[3];  // [B]
    const float* Wq      = (const float*)d_in[4];  // [D,H]
    const float* Wk      = (const float*)d_in[5];  // [D,H]
    const float* wv      = (const float*)d_in[6];  // [H]
    float* out = (float*)d_out;                    // [B,Q,V]

    proj_gemm<<<dim3(H_ / 64, 16 + 128), 128>>>(queries, keys, Wq, Wk, vlens);
    scores_kernel<<<dim3(Q_ / 4, K_ / 256, B_), 256>>>(wv, vlens);
    softmax_norm<<<dim3(Q_ / 4, B_), 256>>>(vlens);
    av_gemm<<<dim3(V_ / 64, Q_ / 64, B_ * SPLITS), 128>>>(values, vlens);
    av_reduce<<<dim3(B_ * Q_ * V_ / 4 / 256), 256>>>(vlens, out);
}

// round 15
// speedup vs baseline: 1.4866x; 1.4866x over previous
#include <cuda_runtime.h>
#include <cstdint>

constexpr int B_ = 8;     // batch
constexpr int Q_ = 128;   // queries
constexpr int K_ = 1024;  // keys
constexpr int D_ = 512;   // qk feature dim
constexpr int H_ = 256;   // hidden
constexpr int V_ = 512;   // value dim
constexpr int MK = B_ * K_;   // 8192 rows of kproj

// Scratch (no cudaMalloc allowed)
__device__ float g_qproj [B_ * Q_ * H_];   // [B*Q][H]   1 MB
__device__ float g_kprojT[H_ * B_ * K_];   // [H][B*K]   8 MB
__device__ float g_scores[B_ * Q_ * K_];   // [B*Q][K]   4 MB (scores -> attn)

__device__ __forceinline__ float tanh_fast(float x) {
    float y;
    asm("tanh.approx.f32 %0, %1;" : "=f"(y) : "f"(x));
    return y;
}
__device__ __forceinline__ unsigned long long pack2(float lo, float hi) {
    unsigned long long r;
    asm("mov.b64 %0, {%1, %2};" : "=l"(r) : "f"(lo), "f"(hi));
    return r;
}
__device__ __forceinline__ float2 unpack2(unsigned long long v) {
    float2 r;
    asm("mov.b64 {%0, %1}, %2;" : "=f"(r.x), "=f"(r.y) : "l"(v));
    return r;
}
__device__ __forceinline__ unsigned long long fma2(unsigned long long a,
                                                   unsigned long long b,
                                                   unsigned long long c) {
    unsigned long long d;
    asm("fma.rn.f32x2 %0, %1, %2, %3;" : "=l"(d) : "l"(a), "l"(b), "l"(c));
    return d;
}
__device__ __forceinline__ unsigned long long add2(unsigned long long a,
                                                   unsigned long long b) {
    unsigned long long d;
    asm("add.rn.f32x2 %0, %1, %2;" : "=l"(d) : "l"(a), "l"(b));
    return d;
}
__device__ __forceinline__ uint32_t f2tf32(float x) {
    uint32_t r;
    asm("cvt.rna.tf32.f32 %0, %1;" : "=r"(r) : "f"(x));
    return r;
}
__device__ __forceinline__ void mma_tf32(float* c, const uint32_t* a, const uint32_t* b) {
    asm volatile(
        "mma.sync.aligned.m16n8k8.row.col.f32.tf32.tf32.f32 "
        "{%0,%1,%2,%3}, {%4,%5,%6,%7}, {%8,%9}, {%0,%1,%2,%3};"
        : "+f"(c[0]), "+f"(c[1]), "+f"(c[2]), "+f"(c[3])
        : "r"(a[0]), "r"(a[1]), "r"(a[2]), "r"(a[3]), "r"(b[0]), "r"(b[1]));
}
__device__ __forceinline__ void named_bar(int id, int count) {
    asm volatile("bar.sync %0, %1;" :: "r"(id), "r"(count) : "memory");
}

// ----------------------------------------------------------------------------
// K1: tensor-core projection GEMM — single-pass tf32 (round-12, measured 31us).
// ----------------------------------------------------------------------------
__global__ __launch_bounds__(128)
void proj_gemm(const float* __restrict__ queries, const float* __restrict__ keys,
               const float* __restrict__ Wq, const float* __restrict__ Wk,
               const int* __restrict__ vlens)
{
    constexpr int BK = 16, PAD = 72;
    __shared__ uint32_t AsHi[2][BK][PAD];
    __shared__ uint32_t Bsm [2][BK][PAD];

    const int tid = threadIdx.x;
    const bool isQ = (blockIdx.y < 16);
    const float* A;
    const float* W;
    long long row0;
    if (isQ) {
        A = queries; W = Wq; row0 = (long long)blockIdx.y * 64;
    } else {
        int r  = (int)(blockIdx.y - 16) * 64;
        int b  = r >> 10;
        int k0 = r & 1023;
        if (k0 >= vlens[b]) return;     // masked kproj tile
        A = keys; W = Wk; row0 = r;
    }
    const int col0 = blockIdx.x * 64;

    const int warp = tid >> 5, lane = tid & 31;
    const int wm = warp >> 1, wn = warp & 1;
    const int gid = lane >> 2, titg = lane & 3;
    const int m_base = wm * 32;
    const int n_base = wn * 32;

    int arow[2], ac4[2], brow[2], bc4[2];
    #pragma unroll
    for (int u = 0; u < 2; u++) {
        int l = tid * 2 + u;
        arow[u] = l >> 2;  ac4[u] = (l & 3) << 2;
        brow[u] = l >> 4;  bc4[u] = (l & 15) << 2;
    }

    float acc[2][4][4];
    #pragma unroll
    for (int mt = 0; mt < 2; mt++)
        #pragma unroll
        for (int nt = 0; nt < 4; nt++)
            #pragma unroll
            for (int i = 0; i < 4; i++) acc[mt][nt][i] = 0.0f;

    float4 avr[2], bvr[2];
    #pragma unroll
    for (int u = 0; u < 2; u++) {
        avr[u] = *(const float4*)(A + (row0 + arow[u]) * D_ + ac4[u]);
        bvr[u] = *(const float4*)(W + (long long)brow[u] * H_ + col0 + bc4[u]);
    }
    #pragma unroll
    for (int u = 0; u < 2; u++) {
        float av[4] = {avr[u].x, avr[u].y, avr[u].z, avr[u].w};
        #pragma unroll
        for (int i = 0; i < 4; i++)
            AsHi[0][ac4[u] + i][arow[u]] = f2tf32(av[i]);
        float bv[4] = {bvr[u].x, bvr[u].y, bvr[u].z, bvr[u].w};
        #pragma unroll
        for (int i = 0; i < 4; i++)
            Bsm[0][brow[u]][bc4[u] + i] = f2tf32(bv[i]);
    }
    __syncthreads();

    constexpr int NKB = D_ / BK;   // 32
    for (int it = 0; it < NKB; it++) {
        const int cur = it & 1;
        if (it + 1 < NKB) {
            const int kb = (it + 1) * BK;
            #pragma unroll
            for (int u = 0; u < 2; u++) {
                avr[u] = *(const float4*)(A + (row0 + arow[u]) * D_ + kb + ac4[u]);
                bvr[u] = *(const float4*)(W + (long long)(kb + brow[u]) * H_ + col0 + bc4[u]);
            }
        }
        #pragma unroll
        for (int ks = 0; ks < 2; ks++) {
            const int k0 = ks * 8 + titg;
            uint32_t ahi[2][4], bf[4][2];
            #pragma unroll
            for (int mt = 0; mt < 2; mt++) {
                const int m = m_base + mt * 16 + gid;
                ahi[mt][0] = AsHi[cur][k0][m];
                ahi[mt][1] = AsHi[cur][k0][m + 8];
                ahi[mt][2] = AsHi[cur][k0 + 4][m];
                ahi[mt][3] = AsHi[cur][k0 + 4][m + 8];
            }
            #pragma unroll
            for (int nt = 0; nt < 4; nt++) {
                const int n = n_base + nt * 8 + gid;
                bf[nt][0] = Bsm[cur][k0][n];
                bf[nt][1] = Bsm[cur][k0 + 4][n];
            }
            #pragma unroll
            for (int mt = 0; mt < 2; mt++)
                #pragma unroll
                for (int nt = 0; nt < 4; nt++)
                    mma_tf32(acc[mt][nt], ahi[mt], bf[nt]);
        }
        if (it + 1 < NKB) {
            const int nxt = 1 - cur;
            #pragma unroll
            for (int u = 0; u < 2; u++) {
                float av[4] = {avr[u].x, avr[u].y, avr[u].z, avr[u].w};
                #pragma unroll
                for (int i = 0; i < 4; i++)
                    AsHi[nxt][ac4[u] + i][arow[u]] = f2tf32(av[i]);
                float bv[4] = {bvr[u].x, bvr[u].y, bvr[u].z, bvr[u].w};
                #pragma unroll
                for (int i = 0; i < 4; i++)
                    Bsm[nxt][brow[u]][bc4[u] + i] = f2tf32(bv[i]);
            }
            __syncthreads();
        }
    }

    if (isQ) {
        #pragma unroll
        for (int mt = 0; mt < 2; mt++) {
            const long long r_lo = row0 + m_base + mt * 16 + gid;
            #pragma unroll
            for (int nt = 0; nt < 4; nt++) {
                const int n = col0 + n_base + nt * 8 + 2 * titg;
                *(float2*)(g_qproj + r_lo * H_ + n) =
                    make_float2(acc[mt][nt][0], acc[mt][nt][1]);
                *(float2*)(g_qproj + (r_lo + 8) * H_ + n) =
                    make_float2(acc[mt][nt][2], acc[mt][nt][3]);
            }
        }
    } else {
        #pragma unroll
        for (int mt = 0; mt < 2; mt++) {
            const long long m = row0 + m_base + mt * 16 + gid;
            #pragma unroll
            for (int nt = 0; nt < 4; nt++) {
                const long long n = col0 + n_base + nt * 8 + 2 * titg;
                g_kprojT[n * MK + m]           = acc[mt][nt][0];
                g_kprojT[(n + 1) * MK + m]     = acc[mt][nt][1];
                g_kprojT[n * MK + m + 8]       = acc[mt][nt][2];
                g_kprojT[(n + 1) * MK + m + 8] = acc[mt][nt][3];
            }
        }
    }
}

// ----------------------------------------------------------------------------
// K2: masked tanh-scores, QT=4 + warp-level mask skip (round-13 version).
// grid = (32, 4, 8), 256 threads.
// ----------------------------------------------------------------------------
__global__ __launch_bounds__(256)
void scores_kernel(const float* __restrict__ wv, const int* __restrict__ vlens)
{
    constexpr int QT = 4;
    constexpr int HC = 16;
    constexpr int NCH = H_ / HC;
    __shared__ float s_tile[2][HC][256];
    __shared__ float s_q[QT][H_];
    __shared__ float s_wv[H_];

    const int b   = blockIdx.z;
    const int kp  = blockIdx.y;
    const int q0  = blockIdx.x * QT;
    const int tid = threadIdx.x;
    const int vlen = vlens[b];
    if (kp * 256 >= vlen) return;
    const bool wactive = (kp * 256 + (tid & ~31)) < vlen;   // warp-uniform

    for (int i = tid; i < QT * H_; i += 256)
        s_q[i >> 8][i & 255] = g_qproj[(long long)(b * Q_ + q0 + (i >> 8)) * H_ + (i & 255)];
    for (int i = tid; i < H_; i += 256) s_wv[i] = wv[i];

    const float* kbase = g_kprojT + (long long)b * K_ + kp * 256;

    float4 rn[4];
    #pragma unroll
    for (int i = 0; i < 4; i++) {
        int idx = i * 256 + tid;
        int h = idx >> 6, c4 = (idx & 63) << 2;
        rn[i] = *(const float4*)(kbase + (long long)h * MK + c4);
    }
    #pragma unroll
    for (int i = 0; i < 4; i++) {
        int idx = i * 256 + tid;
        int h = idx >> 6, c4 = (idx & 63) << 2;
        *(float4*)&s_tile[0][h][c4] = rn[i];
    }
    __syncthreads();

    unsigned long long acc[QT] = {0ull, 0ull, 0ull, 0ull};

    for (int hc = 0; hc < NCH; hc++) {
        const int cur = hc & 1;
        if (hc + 1 < NCH) {
            #pragma unroll
            for (int i = 0; i < 4; i++) {
                int idx = i * 256 + tid;
                int h = idx >> 6, c4 = (idx & 63) << 2;
                rn[i] = *(const float4*)(kbase + (long long)((hc + 1) * HC + h) * MK + c4);
            }
        }
        if (wactive) {
            const int hbase = hc * HC;
            #pragma unroll
            for (int hh = 0; hh < HC; hh += 2) {
                float kv0 = s_tile[cur][hh][tid];
                float kv1 = s_tile[cur][hh + 1][tid];
                unsigned long long kvp = pack2(kv0, kv1);
                unsigned long long wvp = *(const unsigned long long*)&s_wv[hbase + hh];
                #pragma unroll
                for (int j = 0; j < QT; j++) {
                    unsigned long long qp = *(const unsigned long long*)&s_q[j][hbase + hh];
                    float2 sf = unpack2(add2(qp, kvp));
                    unsigned long long t = pack2(tanh_fast(sf.x), tanh_fast(sf.y));
                    acc[j] = fma2(t, wvp, acc[j]);
                }
            }
        }
        if (hc + 1 < NCH) {
            #pragma unroll
            for (int i = 0; i < 4; i++) {
                int idx = i * 256 + tid;
                int h = idx >> 6, c4 = (idx & 63) << 2;
                *(float4*)&s_tile[1 - cur][h][c4] = rn[i];
            }
            __syncthreads();
        }
    }

    const int k = kp * 256 + tid;
    if (k < vlen) {
        #pragma unroll
        for (int j = 0; j < QT; j++) {
            float2 r = unpack2(acc[j]);
            g_scores[(long long)(b * Q_ + q0 + j) * K_ + k] = r.x + r.y;
        }
    }
}

// ----------------------------------------------------------------------------
// K3: masked softmax — normalizes in place; zero-fills [vlen, roundup16(vlen)).
// grid = (32, 8), 256 threads.
// ----------------------------------------------------------------------------
__global__ __launch_bounds__(256)
void softmax_norm(const int* __restrict__ vlens)
{
    constexpr int QT = 4;
    __shared__ float s_sc[QT][K_];
    __shared__ float s_red[8];

    const int b   = blockIdx.y;
    const int q0  = blockIdx.x * QT;
    const int tid = threadIdx.x;
    const int lane = tid & 31;
    const int wid  = tid >> 5;
    const int vlen = vlens[b];
    const int kmax = (vlen + 15) & ~15;

    #pragma unroll
    for (int j = 0; j < QT; j++)
        for (int k = tid; k < vlen; k += 256)
            s_sc[j][k] = g_scores[(long long)(b * Q_ + q0 + j) * K_ + k];
    __syncthreads();

    #pragma unroll 1
    for (int j = 0; j < QT; j++) {
        float m = -3.4e38f;
        for (int k = tid; k < vlen; k += 256) m = fmaxf(m, s_sc[j][k]);
        #pragma unroll
        for (int off = 16; off; off >>= 1)
            m = fmaxf(m, __shfl_xor_sync(0xffffffffu, m, off));
        if (lane == 0) s_red[wid] = m;
        __syncthreads();
        float mm = s_red[0];
        #pragma unroll
        for (int w = 1; w < 8; w++) mm = fmaxf(mm, s_red[w]);
        __syncthreads();

        float s = 0.f;
        for (int k = tid; k < vlen; k += 256) {
            float e = __expf(s_sc[j][k] - mm);
            s_sc[j][k] = e;
            s += e;
        }
        #pragma unroll
        for (int off = 16; off; off >>= 1)
            s += __shfl_xor_sync(0xffffffffu, s, off);
        if (lane == 0) s_red[wid] = s;
        __syncthreads();
        float ssum = 0.f;
        #pragma unroll
        for (int w = 0; w < 8; w++) ssum += s_red[w];
        float inv = 1.0f / ssum;

        float* attn_row = g_scores + (long long)(b * Q_ + q0 + j) * K_;
        for (int k = tid; k < vlen; k += 256)
            attn_row[k] = s_sc[j][k] * inv;
        for (int k = vlen + tid; k < kmax; k += 256)
            attn_row[k] = 0.0f;
        __syncthreads();
    }
}

// ----------------------------------------------------------------------------
// K4: AV GEMM, tf32 MMA, IN-BLOCK split-K: 256 threads = 2 groups of 128.
// Group g computes its half of the k-range into private smem-staged tiles
// (named barriers, so groups free-run); group 1's accumulators are folded
// into group 0's via one smem tile, then group 0 writes out.
// grid = (V/64=8, Q/64=2, B=8) = 128 blocks.
// ----------------------------------------------------------------------------
__global__ __launch_bounds__(256)
void av_gemm(const float* __restrict__ values, const int* __restrict__ vlens,
             float* __restrict__ out)
{
    constexpr int BK = 16, PAD = 72;
    __shared__ uint32_t AsHi[2][2][BK][PAD];   // [group][buf]
    __shared__ uint32_t Bsm [2][2][BK][PAD];
    __shared__ float s_acc[64][66];            // reduction tile

    const int tid = threadIdx.x;
    const int g   = tid >> 7;          // group 0/1
    const int tg  = tid & 127;         // tid within group
    const int b   = blockIdx.z;
    const int vlen = vlens[b];
    const int kmax = (vlen + 15) & ~15;
    const int NKBt = kmax / BK;                 // 1..64
    const int NKB0 = (NKBt + 1) >> 1;
    const int it_beg = g ? NKB0 : 0;
    const int it_end = g ? NKBt : NKB0;
    const int my_nkb = it_end - it_beg;         // group-uniform

    const long long row0 = (long long)b * Q_ + blockIdx.y * 64;
    const int col0 = blockIdx.x * 64;
    const float* A  = g_scores + it_beg * BK;                            // row stride K_
    const float* Bv = values + (long long)b * K_ * V_ + (long long)it_beg * BK * V_;

    const int warp = tg >> 5, lane = tg & 31;
    const int wm = warp >> 1, wn = warp & 1;
    const int gid = lane >> 2, titg = lane & 3;
    const int m_base = wm * 32;
    const int n_base = wn * 32;
    const int barid = g + 1;

    int arow[2], ac4[2], brow[2], bc4[2];
    #pragma unroll
    for (int u = 0; u < 2; u++) {
        int l = tg * 2 + u;
        arow[u] = l >> 2;  ac4[u] = (l & 3) << 2;
        brow[u] = l >> 4;  bc4[u] = (l & 15) << 2;
    }

    float acc[2][4][4];
    #pragma unroll
    for (int mt = 0; mt < 2; mt++)
        #pragma unroll
        for (int nt = 0; nt < 4; nt++)
            #pragma unroll
            for (int i = 0; i < 4; i++) acc[mt][nt][i] = 0.0f;

    if (my_nkb > 0) {
        float4 avr[2], bvr[2];
        #pragma unroll
        for (int u = 0; u < 2; u++) {
            avr[u] = *(const float4*)(A + (row0 + arow[u]) * K_ + ac4[u]);
            bvr[u] = *(const float4*)(Bv + (long long)brow[u] * V_ + col0 + bc4[u]);
        }
        #pragma unroll
        for (int u = 0; u < 2; u++) {
            float av[4] = {avr[u].x, avr[u].y, avr[u].z, avr[u].w};
            #pragma unroll
            for (int i = 0; i < 4; i++)
                AsHi[g][0][ac4[u] + i][arow[u]] = f2tf32(av[i]);
            float bv[4] = {bvr[u].x, bvr[u].y, bvr[u].z, bvr[u].w};
            #pragma unroll
            for (int i = 0; i < 4; i++)
                Bsm[g][0][brow[u]][bc4[u] + i] = f2tf32(bv[i]);
        }
        named_bar(barid, 128);

        for (int it = 0; it < my_nkb; it++) {
            const int cur = it & 1;
            if (it + 1 < my_nkb) {
                const int kb = (it + 1) * BK;
                #pragma unroll
                for (int u = 0; u < 2; u++) {
                    avr[u] = *(const float4*)(A + (row0 + arow[u]) * K_ + kb + ac4[u]);
                    bvr[u] = *(const float4*)(Bv + (long long)(kb + brow[u]) * V_ + col0 + bc4[u]);
                }
            }
            #pragma unroll
            for (int ks = 0; ks < 2; ks++) {
                const int k0 = ks * 8 + titg;
                uint32_t ahi[2][4], bf[4][2];
                #pragma unroll
                for (int mt = 0; mt < 2; mt++) {
                    const int m = m_base + mt * 16 + gid;
                    ahi[mt][0] = AsHi[g][cur][k0][m];
                    ahi[mt][1] = AsHi[g][cur][k0][m + 8];
                    ahi[mt][2] = AsHi[g][cur][k0 + 4][m];
                    ahi[mt][3] = AsHi[g][cur][k0 + 4][m + 8];
                }
                #pragma unroll
                for (int nt = 0; nt < 4; nt++) {
                    const int n = n_base + nt * 8 + gid;
                    bf[nt][0] = Bsm[g][cur][k0][n];
                    bf[nt][1] = Bsm[g][cur][k0 + 4][n];
                }
                #pragma unroll
                for (int mt = 0; mt < 2; mt++)
                    #pragma unroll
                    for (int nt = 0; nt < 4; nt++)
                        mma_tf32(acc[mt][nt], ahi[mt], bf[nt]);
            }
            if (it + 1 < my_nkb) {
                const int nxt = 1 - cur;
                #pragma unroll
                for (int u = 0; u < 2; u++) {
                    float av[4] = {avr[u].x, avr[u].y, avr[u].z, avr[u].w};
                    #pragma unroll
                    for (int i = 0; i < 4; i++)
                        AsHi[g][nxt][ac4[u] + i][arow[u]] = f2tf32(av[i]);
                    float bv[4] = {bvr[u].x, bvr[u].y, bvr[u].z, bvr[u].w};
                    #pragma unroll
                    for (int i = 0; i < 4; i++)
                        Bsm[g][nxt][brow[u]][bc4[u] + i] = f2tf32(bv[i]);
                }
                named_bar(barid, 128);
            }
        }
    }

    // ---- in-block split-K reduction ----
    if (g == 1) {
        #pragma unroll
        for (int mt = 0; mt < 2; mt++) {
            const int m = m_base + mt * 16 + gid;
            #pragma unroll
            for (int nt = 0; nt < 4; nt++) {
                const int n = n_base + nt * 8 + 2 * titg;
                s_acc[m][n]         = acc[mt][nt][0];
                s_acc[m][n + 1]     = acc[mt][nt][1];
                s_acc[m + 8][n]     = acc[mt][nt][2];
                s_acc[m + 8][n + 1] = acc[mt][nt][3];
            }
        }
    }
    __syncthreads();
    if (g == 0) {
        #pragma unroll
        for (int mt = 0; mt < 2; mt++) {
            const int m = m_base + mt * 16 + gid;
            const long long r_lo = row0 + m;
            #pragma unroll
            for (int nt = 0; nt < 4; nt++) {
                const int n = n_base + nt * 8 + 2 * titg;
                float2 o0 = make_float2(acc[mt][nt][0] + s_acc[m][n],
                                        acc[mt][nt][1] + s_acc[m][n + 1]);
                float2 o1 = make_float2(acc[mt][nt][2] + s_acc[m + 8][n],
                                        acc[mt][nt][3] + s_acc[m + 8][n + 1]);
                *(float2*)(out + r_lo * V_ + col0 + n)       = o0;
                *(float2*)(out + (r_lo + 8) * V_ + col0 + n) = o1;
            }
        }
    }
}

// ----------------------------------------------------------------------------
extern "C" void kernel_launch(void* const* d_in, const int* in_sizes, int n_in,
                              void* d_out, int out_size)
{
    const float* queries = (const float*)d_in[0];  // [B,Q,D]
    const float* keys    = (const float*)d_in[1];  // [B,K,D]
    const float* values  = (const float*)d_in[2];  // [B,K,V]
    const int*   vlens   = (const int*)  d_in[3];  // [B]
    const float* Wq      = (const float*)d_in[4];  // [D,H]
    const float* Wk      = (const float*)d_in[5];  // [D,H]
    const float* wv      = (const float*)d_in[6];  // [H]
    float* out = (float*)d_out;                    // [B,Q,V]

    proj_gemm<<<dim3(H_ / 64, 16 + 128), 128>>>(queries, keys, Wq, Wk, vlens);
    scores_kernel<<<dim3(Q_ / 4, K_ / 256, B_), 256>>>(wv, vlens);
    softmax_norm<<<dim3(Q_ / 4, B_), 256>>>(vlens);
    av_gemm<<<dim3(V_ / 64, Q_ / 64, B_), 256>>>(values, vlens, out);
}

// round 16
// speedup vs baseline: 1.5485x; 1.0416x over previous
#include <cuda_runtime.h>
#include <cstdint>

constexpr int B_ = 8;     // batch
constexpr int Q_ = 128;   // queries
constexpr int K_ = 1024;  // keys
constexpr int D_ = 512;   // qk feature dim
constexpr int H_ = 256;   // hidden
constexpr int V_ = 512;   // value dim
constexpr int MK = B_ * K_;   // 8192 rows of kproj

// Scratch (no cudaMalloc allowed)
__device__ float g_qproj [B_ * Q_ * H_];   // [B*Q][H]   1 MB
__device__ float g_kprojT[H_ * B_ * K_];   // [H][B*K]   8 MB
__device__ float g_scores[B_ * Q_ * K_];   // [B*Q][K]   4 MB (scores -> attn)

__device__ __forceinline__ float tanh_fast(float x) {
    float y;
    asm("tanh.approx.f32 %0, %1;" : "=f"(y) : "f"(x));
    return y;
}
__device__ __forceinline__ unsigned long long pack2(float lo, float hi) {
    unsigned long long r;
    asm("mov.b64 %0, {%1, %2};" : "=l"(r) : "f"(lo), "f"(hi));
    return r;
}
__device__ __forceinline__ float2 unpack2(unsigned long long v) {
    float2 r;
    asm("mov.b64 {%0, %1}, %2;" : "=f"(r.x), "=f"(r.y) : "l"(v));
    return r;
}
__device__ __forceinline__ unsigned long long fma2(unsigned long long a,
                                                   unsigned long long b,
                                                   unsigned long long c) {
    unsigned long long d;
    asm("fma.rn.f32x2 %0, %1, %2, %3;" : "=l"(d) : "l"(a), "l"(b), "l"(c));
    return d;
}
__device__ __forceinline__ unsigned long long add2(unsigned long long a,
                                                   unsigned long long b) {
    unsigned long long d;
    asm("add.rn.f32x2 %0, %1, %2;" : "=l"(d) : "l"(a), "l"(b));
    return d;
}
__device__ __forceinline__ uint32_t f2tf32(float x) {
    uint32_t r;
    asm("cvt.rna.tf32.f32 %0, %1;" : "=r"(r) : "f"(x));
    return r;
}
__device__ __forceinline__ void mma_tf32(float* c, const uint32_t* a, const uint32_t* b) {
    asm volatile(
        "mma.sync.aligned.m16n8k8.row.col.f32.tf32.tf32.f32 "
        "{%0,%1,%2,%3}, {%4,%5,%6,%7}, {%8,%9}, {%0,%1,%2,%3};"
        : "+f"(c[0]), "+f"(c[1]), "+f"(c[2]), "+f"(c[3])
        : "r"(a[0]), "r"(a[1]), "r"(a[2]), "r"(a[3]), "r"(b[0]), "r"(b[1]));
}
__device__ __forceinline__ void named_bar(int id, int count) {
    asm volatile("bar.sync %0, %1;" :: "r"(id), "r"(count) : "memory");
}

// ----------------------------------------------------------------------------
// K1: tensor-core projection GEMM — single-pass tf32 (round-12, measured 31us).
// ----------------------------------------------------------------------------
__global__ __launch_bounds__(128)
void proj_gemm(const float* __restrict__ queries, const float* __restrict__ keys,
               const float* __restrict__ Wq, const float* __restrict__ Wk,
               const int* __restrict__ vlens)
{
    constexpr int BK = 16, PAD = 72;
    __shared__ uint32_t AsHi[2][BK][PAD];
    __shared__ uint32_t Bsm [2][BK][PAD];

    const int tid = threadIdx.x;
    const bool isQ = (blockIdx.y < 16);
    const float* A;
    const float* W;
    long long row0;
    if (isQ) {
        A = queries; W = Wq; row0 = (long long)blockIdx.y * 64;
    } else {
        int r  = (int)(blockIdx.y - 16) * 64;
        int b  = r >> 10;
        int k0 = r & 1023;
        if (k0 >= vlens[b]) return;     // masked kproj tile
        A = keys; W = Wk; row0 = r;
    }
    const int col0 = blockIdx.x * 64;

    const int warp = tid >> 5, lane = tid & 31;
    const int wm = warp >> 1, wn = warp & 1;
    const int gid = lane >> 2, titg = lane & 3;
    const int m_base = wm * 32;
    const int n_base = wn * 32;

    int arow[2], ac4[2], brow[2], bc4[2];
    #pragma unroll
    for (int u = 0; u < 2; u++) {
        int l = tid * 2 + u;
        arow[u] = l >> 2;  ac4[u] = (l & 3) << 2;
        brow[u] = l >> 4;  bc4[u] = (l & 15) << 2;
    }

    float acc[2][4][4];
    #pragma unroll
    for (int mt = 0; mt < 2; mt++)
        #pragma unroll
        for (int nt = 0; nt < 4; nt++)
            #pragma unroll
            for (int i = 0; i < 4; i++) acc[mt][nt][i] = 0.0f;

    float4 avr[2], bvr[2];
    #pragma unroll
    for (int u = 0; u < 2; u++) {
        avr[u] = *(const float4*)(A + (row0 + arow[u]) * D_ + ac4[u]);
        bvr[u] = *(const float4*)(W + (long long)brow[u] * H_ + col0 + bc4[u]);
    }
    #pragma unroll
    for (int u = 0; u < 2; u++) {
        float av[4] = {avr[u].x, avr[u].y, avr[u].z, avr[u].w};
        #pragma unroll
        for (int i = 0; i < 4; i++)
            AsHi[0][ac4[u] + i][arow[u]] = f2tf32(av[i]);
        float bv[4] = {bvr[u].x, bvr[u].y, bvr[u].z, bvr[u].w};
        #pragma unroll
        for (int i = 0; i < 4; i++)
            Bsm[0][brow[u]][bc4[u] + i] = f2tf32(bv[i]);
    }
    __syncthreads();

    constexpr int NKB = D_ / BK;   // 32
    for (int it = 0; it < NKB; it++) {
        const int cur = it & 1;
        if (it + 1 < NKB) {
            const int kb = (it + 1) * BK;
            #pragma unroll
            for (int u = 0; u < 2; u++) {
                avr[u] = *(const float4*)(A + (row0 + arow[u]) * D_ + kb + ac4[u]);
                bvr[u] = *(const float4*)(W + (long long)(kb + brow[u]) * H_ + col0 + bc4[u]);
            }
        }
        #pragma unroll
        for (int ks = 0; ks < 2; ks++) {
            const int k0 = ks * 8 + titg;
            uint32_t ahi[2][4], bf[4][2];
            #pragma unroll
            for (int mt = 0; mt < 2; mt++) {
                const int m = m_base + mt * 16 + gid;
                ahi[mt][0] = AsHi[cur][k0][m];
                ahi[mt][1] = AsHi[cur][k0][m + 8];
                ahi[mt][2] = AsHi[cur][k0 + 4][m];
                ahi[mt][3] = AsHi[cur][k0 + 4][m + 8];
            }
            #pragma unroll
            for (int nt = 0; nt < 4; nt++) {
                const int n = n_base + nt * 8 + gid;
                bf[nt][0] = Bsm[cur][k0][n];
                bf[nt][1] = Bsm[cur][k0 + 4][n];
            }
            #pragma unroll
            for (int mt = 0; mt < 2; mt++)
                #pragma unroll
                for (int nt = 0; nt < 4; nt++)
                    mma_tf32(acc[mt][nt], ahi[mt], bf[nt]);
        }
        if (it + 1 < NKB) {
            const int nxt = 1 - cur;
            #pragma unroll
            for (int u = 0; u < 2; u++) {
                float av[4] = {avr[u].x, avr[u].y, avr[u].z, avr[u].w};
                #pragma unroll
                for (int i = 0; i < 4; i++)
                    AsHi[nxt][ac4[u] + i][arow[u]] = f2tf32(av[i]);
                float bv[4] = {bvr[u].x, bvr[u].y, bvr[u].z, bvr[u].w};
                #pragma unroll
                for (int i = 0; i < 4; i++)
                    Bsm[nxt][brow[u]][bc4[u] + i] = f2tf32(bv[i]);
            }
            __syncthreads();
        }
    }

    if (isQ) {
        #pragma unroll
        for (int mt = 0; mt < 2; mt++) {
            const long long r_lo = row0 + m_base + mt * 16 + gid;
            #pragma unroll
            for (int nt = 0; nt < 4; nt++) {
                const int n = col0 + n_base + nt * 8 + 2 * titg;
                *(float2*)(g_qproj + r_lo * H_ + n) =
                    make_float2(acc[mt][nt][0], acc[mt][nt][1]);
                *(float2*)(g_qproj + (r_lo + 8) * H_ + n) =
                    make_float2(acc[mt][nt][2], acc[mt][nt][3]);
            }
        }
    } else {
        #pragma unroll
        for (int mt = 0; mt < 2; mt++) {
            const long long m = row0 + m_base + mt * 16 + gid;
            #pragma unroll
            for (int nt = 0; nt < 4; nt++) {
                const long long n = col0 + n_base + nt * 8 + 2 * titg;
                g_kprojT[n * MK + m]           = acc[mt][nt][0];
                g_kprojT[(n + 1) * MK + m]     = acc[mt][nt][1];
                g_kprojT[n * MK + m + 8]       = acc[mt][nt][2];
                g_kprojT[(n + 1) * MK + m + 8] = acc[mt][nt][3];
            }
        }
    }
}

// ----------------------------------------------------------------------------
// K2: masked tanh-scores, QT=4 + warp-level mask skip (unchanged).
// grid = (32, 4, 8), 256 threads.
// ----------------------------------------------------------------------------
__global__ __launch_bounds__(256)
void scores_kernel(const float* __restrict__ wv, const int* __restrict__ vlens)
{
    constexpr int QT = 4;
    constexpr int HC = 16;
    constexpr int NCH = H_ / HC;
    __shared__ float s_tile[2][HC][256];
    __shared__ float s_q[QT][H_];
    __shared__ float s_wv[H_];

    const int b   = blockIdx.z;
    const int kp  = blockIdx.y;
    const int q0  = blockIdx.x * QT;
    const int tid = threadIdx.x;
    const int vlen = vlens[b];
    if (kp * 256 >= vlen) return;
    const bool wactive = (kp * 256 + (tid & ~31)) < vlen;   // warp-uniform

    for (int i = tid; i < QT * H_; i += 256)
        s_q[i >> 8][i & 255] = g_qproj[(long long)(b * Q_ + q0 + (i >> 8)) * H_ + (i & 255)];
    for (int i = tid; i < H_; i += 256) s_wv[i] = wv[i];

    const float* kbase = g_kprojT + (long long)b * K_ + kp * 256;

    float4 rn[4];
    #pragma unroll
    for (int i = 0; i < 4; i++) {
        int idx = i * 256 + tid;
        int h = idx >> 6, c4 = (idx & 63) << 2;
        rn[i] = *(const float4*)(kbase + (long long)h * MK + c4);
    }
    #pragma unroll
    for (int i = 0; i < 4; i++) {
        int idx = i * 256 + tid;
        int h = idx >> 6, c4 = (idx & 63) << 2;
        *(float4*)&s_tile[0][h][c4] = rn[i];
    }
    __syncthreads();

    unsigned long long acc[QT] = {0ull, 0ull, 0ull, 0ull};

    for (int hc = 0; hc < NCH; hc++) {
        const int cur = hc & 1;
        if (hc + 1 < NCH) {
            #pragma unroll
            for (int i = 0; i < 4; i++) {
                int idx = i * 256 + tid;
                int h = idx >> 6, c4 = (idx & 63) << 2;
                rn[i] = *(const float4*)(kbase + (long long)((hc + 1) * HC + h) * MK + c4);
            }
        }
        if (wactive) {
            const int hbase = hc * HC;
            #pragma unroll
            for (int hh = 0; hh < HC; hh += 2) {
                float kv0 = s_tile[cur][hh][tid];
                float kv1 = s_tile[cur][hh + 1][tid];
                unsigned long long kvp = pack2(kv0, kv1);
                unsigned long long wvp = *(const unsigned long long*)&s_wv[hbase + hh];
                #pragma unroll
                for (int j = 0; j < QT; j++) {
                    unsigned long long qp = *(const unsigned long long*)&s_q[j][hbase + hh];
                    float2 sf = unpack2(add2(qp, kvp));
                    unsigned long long t = pack2(tanh_fast(sf.x), tanh_fast(sf.y));
                    acc[j] = fma2(t, wvp, acc[j]);
                }
            }
        }
        if (hc + 1 < NCH) {
            #pragma unroll
            for (int i = 0; i < 4; i++) {
                int idx = i * 256 + tid;
                int h = idx >> 6, c4 = (idx & 63) << 2;
                *(float4*)&s_tile[1 - cur][h][c4] = rn[i];
            }
            __syncthreads();
        }
    }

    const int k = kp * 256 + tid;
    if (k < vlen) {
        #pragma unroll
        for (int j = 0; j < QT; j++) {
            float2 r = unpack2(acc[j]);
            g_scores[(long long)(b * Q_ + q0 + j) * K_ + k] = r.x + r.y;
        }
    }
}

// ----------------------------------------------------------------------------
// K3: masked softmax — normalizes in place; zero-fills [vlen, roundup16(vlen)).
// grid = (32, 8), 256 threads.
// ----------------------------------------------------------------------------
__global__ __launch_bounds__(256)
void softmax_norm(const int* __restrict__ vlens)
{
    constexpr int QT = 4;
    __shared__ float s_sc[QT][K_];
    __shared__ float s_red[8];

    const int b   = blockIdx.y;
    const int q0  = blockIdx.x * QT;
    const int tid = threadIdx.x;
    const int lane = tid & 31;
    const int wid  = tid >> 5;
    const int vlen = vlens[b];
    const int kmax = (vlen + 15) & ~15;

    #pragma unroll
    for (int j = 0; j < QT; j++)
        for (int k = tid; k < vlen; k += 256)
            s_sc[j][k] = g_scores[(long long)(b * Q_ + q0 + j) * K_ + k];
    __syncthreads();

    #pragma unroll 1
    for (int j = 0; j < QT; j++) {
        float m = -3.4e38f;
        for (int k = tid; k < vlen; k += 256) m = fmaxf(m, s_sc[j][k]);
        #pragma unroll
        for (int off = 16; off; off >>= 1)
            m = fmaxf(m, __shfl_xor_sync(0xffffffffu, m, off));
        if (lane == 0) s_red[wid] = m;
        __syncthreads();
        float mm = s_red[0];
        #pragma unroll
        for (int w = 1; w < 8; w++) mm = fmaxf(mm, s_red[w]);
        __syncthreads();

        float s = 0.f;
        for (int k = tid; k < vlen; k += 256) {
            float e = __expf(s_sc[j][k] - mm);
            s_sc[j][k] = e;
            s += e;
        }
        #pragma unroll
        for (int off = 16; off; off >>= 1)
            s += __shfl_xor_sync(0xffffffffu, s, off);
        if (lane == 0) s_red[wid] = s;
        __syncthreads();
        float ssum = 0.f;
        #pragma unroll
        for (int w = 0; w < 8; w++) ssum += s_red[w];
        float inv = 1.0f / ssum;

        float* attn_row = g_scores + (long long)(b * Q_ + q0 + j) * K_;
        for (int k = tid; k < vlen; k += 256)
            attn_row[k] = s_sc[j][k] * inv;
        for (int k = vlen + tid; k < kmax; k += 256)
            attn_row[k] = 0.0f;
        __syncthreads();
    }
}

// ----------------------------------------------------------------------------
// K4: AV GEMM, tf32 MMA, 4-WAY in-block split-K: 512 threads = 4 groups of 128.
// Per-group double-buffered tiles (named barriers). Reduction tiles are
// ALIASED onto the dead tile smem after compute. Deterministic tree:
// final = (acc0+acc2) + (acc1+acc3).
// grid = (V/64=8, Q/64=2, B=8) = 128 blocks.
// ----------------------------------------------------------------------------
constexpr int GRP_BYTES = 2 * 2 * 16 * 72 * 4;   // 18432 B per group region

__global__ __launch_bounds__(512)
void av_gemm(const float* __restrict__ values, const int* __restrict__ vlens,
             float* __restrict__ out)
{
    constexpr int BK = 16;
    __shared__ __align__(16) unsigned char s_raw[4][GRP_BYTES];   // 72 KB

    const int tid = threadIdx.x;
    const int g   = tid >> 7;          // group 0..3
    const int tg  = tid & 127;
    const int b   = blockIdx.z;
    const int vlen = vlens[b];
    const int kmax = (vlen + 15) & ~15;
    const int NKBt = kmax / BK;                 // 1..64
    const int chunk = (NKBt + 3) >> 2;
    const int it_beg = min(g * chunk, NKBt);
    const int it_end = min(it_beg + chunk, NKBt);
    const int my_nkb = it_end - it_beg;         // group-uniform

    // per-group tile views: AsHi[buf][k][72], Bsm[buf][k][72]
    uint32_t (*AsHi)[BK][72] = reinterpret_cast<uint32_t(*)[BK][72]>(s_raw[g]);
    uint32_t (*Bsm )[BK][72] = reinterpret_cast<uint32_t(*)[BK][72]>(s_raw[g] + GRP_BYTES / 2);

    const long long row0 = (long long)b * Q_ + blockIdx.y * 64;
    const int col0 = blockIdx.x * 64;
    const float* A  = g_scores + it_beg * BK;                            // row stride K_
    const float* Bv = values + (long long)b * K_ * V_ + (long long)it_beg * BK * V_;

    const int warp = tg >> 5, lane = tg & 31;
    const int wm = warp >> 1, wn = warp & 1;
    const int gid = lane >> 2, titg = lane & 3;
    const int m_base = wm * 32;
    const int n_base = wn * 32;
    const int barid = g + 1;

    int arow[2], ac4[2], brow[2], bc4[2];
    #pragma unroll
    for (int u = 0; u < 2; u++) {
        int l = tg * 2 + u;
        arow[u] = l >> 2;  ac4[u] = (l & 3) << 2;
        brow[u] = l >> 4;  bc4[u] = (l & 15) << 2;
    }

    float acc[2][4][4];
    #pragma unroll
    for (int mt = 0; mt < 2; mt++)
        #pragma unroll
        for (int nt = 0; nt < 4; nt++)
            #pragma unroll
            for (int i = 0; i < 4; i++) acc[mt][nt][i] = 0.0f;

    if (my_nkb > 0) {
        float4 avr[2], bvr[2];
        #pragma unroll
        for (int u = 0; u < 2; u++) {
            avr[u] = *(const float4*)(A + (row0 + arow[u]) * K_ + ac4[u]);
            bvr[u] = *(const float4*)(Bv + (long long)brow[u] * V_ + col0 + bc4[u]);
        }
        #pragma unroll
        for (int u = 0; u < 2; u++) {
            float av[4] = {avr[u].x, avr[u].y, avr[u].z, avr[u].w};
            #pragma unroll
            for (int i = 0; i < 4; i++)
                AsHi[0][ac4[u] + i][arow[u]] = f2tf32(av[i]);
            float bv[4] = {bvr[u].x, bvr[u].y, bvr[u].z, bvr[u].w};
            #pragma unroll
            for (int i = 0; i < 4; i++)
                Bsm[0][brow[u]][bc4[u] + i] = f2tf32(bv[i]);
        }
        named_bar(barid, 128);

        for (int it = 0; it < my_nkb; it++) {
            const int cur = it & 1;
            if (it + 1 < my_nkb) {
                const int kb = (it + 1) * BK;
                #pragma unroll
                for (int u = 0; u < 2; u++) {
                    avr[u] = *(const float4*)(A + (row0 + arow[u]) * K_ + kb + ac4[u]);
                    bvr[u] = *(const float4*)(Bv + (long long)(kb + brow[u]) * V_ + col0 + bc4[u]);
                }
            }
            #pragma unroll
            for (int ks = 0; ks < 2; ks++) {
                const int k0 = ks * 8 + titg;
                uint32_t ahi[2][4], bf[4][2];
                #pragma unroll
                for (int mt = 0; mt < 2; mt++) {
                    const int m = m_base + mt * 16 + gid;
                    ahi[mt][0] = AsHi[cur][k0][m];
                    ahi[mt][1] = AsHi[cur][k0][m + 8];
                    ahi[mt][2] = AsHi[cur][k0 + 4][m];
                    ahi[mt][3] = AsHi[cur][k0 + 4][m + 8];
                }
                #pragma unroll
                for (int nt = 0; nt < 4; nt++) {
                    const int n = n_base + nt * 8 + gid;
                    bf[nt][0] = Bsm[cur][k0][n];
                    bf[nt][1] = Bsm[cur][k0 + 4][n];
                }
                #pragma unroll
                for (int mt = 0; mt < 2; mt++)
                    #pragma unroll
                    for (int nt = 0; nt < 4; nt++)
                        mma_tf32(acc[mt][nt], ahi[mt], bf[nt]);
            }
            if (it + 1 < my_nkb) {
                const int nxt = 1 - cur;
                #pragma unroll
                for (int u = 0; u < 2; u++) {
                    float av[4] = {avr[u].x, avr[u].y, avr[u].z, avr[u].w};
                    #pragma unroll
                    for (int i = 0; i < 4; i++)
                        AsHi[nxt][ac4[u] + i][arow[u]] = f2tf32(av[i]);
                    float bv[4] = {bvr[u].x, bvr[u].y, bvr[u].z, bvr[u].w};
                    #pragma unroll
                    for (int i = 0; i < 4; i++)
                        Bsm[nxt][brow[u]][bc4[u] + i] = f2tf32(bv[i]);
                }
                named_bar(barid, 128);
            }
        }
    }

    // ---- aliased in-block split-K reduction: (acc0+acc2)+(acc1+acc3) ----
    __syncthreads();   // all tile compute done; tile smem is dead -> alias
    // reduction tile for group gg lives at s_raw[gg]: float [64][66]
    #define RED_TILE(gg) (reinterpret_cast<float(*)[66]>(s_raw[(gg)]))

    if (g >= 2) {
        float (*t)[66] = RED_TILE(g);
        #pragma unroll
        for (int mt = 0; mt < 2; mt++) {
            const int m = m_base + mt * 16 + gid;
            #pragma unroll
            for (int nt = 0; nt < 4; nt++) {
                const int n = n_base + nt * 8 + 2 * titg;
                t[m][n]         = acc[mt][nt][0];
                t[m][n + 1]     = acc[mt][nt][1];
                t[m + 8][n]     = acc[mt][nt][2];
                t[m + 8][n + 1] = acc[mt][nt][3];
            }
        }
    }
    __syncthreads();
    if (g < 2) {
        float (*t)[66] = RED_TILE(g + 2);
        #pragma unroll
        for (int mt = 0; mt < 2; mt++) {
            const int m = m_base + mt * 16 + gid;
            #pragma unroll
            for (int nt = 0; nt < 4; nt++) {
                const int n = n_base + nt * 8 + 2 * titg;
                acc[mt][nt][0] += t[m][n];
                acc[mt][nt][1] += t[m][n + 1];
                acc[mt][nt][2] += t[m + 8][n];
                acc[mt][nt][3] += t[m + 8][n + 1];
            }
        }
    }
    __syncthreads();
    if (g == 1) {
        float (*t)[66] = RED_TILE(1);
        #pragma unroll
        for (int mt = 0; mt < 2; mt++) {
            const int m = m_base + mt * 16 + gid;
            #pragma unroll
            for (int nt = 0; nt < 4; nt++) {
                const int n = n_base + nt * 8 + 2 * titg;
                t[m][n]         = acc[mt][nt][0];
                t[m][n + 1]     = acc[mt][nt][1];
                t[m + 8][n]     = acc[mt][nt][2];
                t[m + 8][n + 1] = acc[mt][nt][3];
            }
        }
    }
    __syncthreads();
    if (g == 0) {
        float (*t)[66] = RED_TILE(1);
        #pragma unroll
        for (int mt = 0; mt < 2; mt++) {
            const int m = m_base + mt * 16 + gid;
            const long long r_lo = row0 + m;
            #pragma unroll
            for (int nt = 0; nt < 4; nt++) {
                const int n = n_base + nt * 8 + 2 * titg;
                float2 o0 = make_float2(acc[mt][nt][0] + t[m][n],
                                        acc[mt][nt][1] + t[m][n + 1]);
                float2 o1 = make_float2(acc[mt][nt][2] + t[m + 8][n],
                                        acc[mt][nt][3] + t[m + 8][n + 1]);
                *(float2*)(out + r_lo * V_ + col0 + n)       = o0;
                *(float2*)(out + (r_lo + 8) * V_ + col0 + n) = o1;
            }
        }
    }
    #undef RED_TILE
}

// ----------------------------------------------------------------------------
extern "C" void kernel_launch(void* const* d_in, const int* in_sizes, int n_in,
                              void* d_out, int out_size)
{
    const float* queries = (const float*)d_in[0];  // [B,Q,D]
    const float* keys    = (const float*)d_in[1];  // [B,K,D]
    const float* values  = (const float*)d_in[2];  // [B,K,V]
    const int*   vlens   = (const int*)  d_in[3];  // [B]
    const float* Wq      = (const float*)d_in[4];  // [D,H]
    const float* Wk      = (const float*)d_in[5];  // [D,H]
    const float* wv      = (const float*)d_in[6];  // [H]
    float* out = (float*)d_out;                    // [B,Q,V]

    proj_gemm<<<dim3(H_ / 64, 16 + 128), 128>>>(queries, keys, Wq, Wk, vlens);
    scores_kernel<<<dim3(Q_ / 4, K_ / 256, B_), 256>>>(wv, vlens);
    softmax_norm<<<dim3(Q_ / 4, B_), 256>>>(vlens);
    av_gemm<<<dim3(V_ / 64, Q_ / 64, B_), 512>>>(values, vlens, out);
}